// round 14
// baseline (speedup 1.0000x reference)
#include <cuda_runtime.h>
#include <cuda_bf16.h>

#define N_NODES 100000
#define N_EDGES 1000000
#define HID 64
#define IN_DIM 8
#define N_LAYERS 3
#define LN_EPS 1e-5f
#define LRELU 0.2f

// Persistent scratch. h ping-pongs between bufA/bufB so NO kernel ever
// reads and writes the same buffer (the R5-R13 bug was an in-place
// residual write through a __restrict__ pointer aliasing g_h -> UB).
__device__ float g_bufA[(size_t)N_NODES * HID];
__device__ float g_bufB[(size_t)N_NODES * HID];
__device__ float g_hn[(size_t)N_NODES * HID];
__device__ float g_acc[(size_t)N_NODES * HID];
__device__ int   g_row[N_EDGES];
__device__ int   g_col[N_EDGES];
__device__ int   g_is64;
// Telemetry.
__device__ int   g_vmask;
__device__ float g_eagg[2 * HID];
__device__ float g_hself_probe[2 * HID];
__device__ float g_snap[2 * HID];
__device__ float g_oprobe[2 * HID];

// ---------------------------------------------------------------------------
__global__ void v_reset() {
    int t = threadIdx.x;
    if (t == 0) g_vmask = 0;
    if (t < 2 * HID) {
        g_eagg[t] = 0.f; g_hself_probe[t] = 0.f;
        g_snap[t] = 0.f; g_oprobe[t] = 0.f;
    }
}

__global__ void detect_kernel(const int* __restrict__ ei32) {
    int z = 0;
#pragma unroll
    for (int i = 0; i < 64; i++) z |= ei32[2 * i + 1];
    g_is64 = (z == 0) ? 1 : 0;
}

__global__ void convert_kernel(const void* ei) {
    int e = blockIdx.x * blockDim.x + threadIdx.x;
    if (e >= N_EDGES) return;
    if (g_is64) {
        const long long* p = (const long long*)ei;
        g_row[e] = (int)p[e];
        g_col[e] = (int)p[N_EDGES + e];
    } else {
        const int* p = (const int*)ei;
        g_row[e] = p[e];
        g_col[e] = p[N_EDGES + e];
    }
}

// ---------------------------------------------------------------------------
// Input projection: h = x @ Wp^T + bp.  32 nodes per 256-thread block.
// ---------------------------------------------------------------------------
__global__ void proj_kernel(const float* __restrict__ x,
                            const float* __restrict__ Wp,
                            const float* __restrict__ bp,
                            float* dst) {
    __shared__ float sWt[IN_DIM * HID];
    __shared__ float sb[HID];
    __shared__ float sx[32 * IN_DIM];

    int t = threadIdx.x;
    if (t < HID) sb[t] = bp[t];
    for (int i = t; i < HID * IN_DIM; i += 256) {
        int f = i >> 3, k = i & 7;
        sWt[k * HID + f] = Wp[i];
    }
    int nbase = blockIdx.x * 32;
    sx[t] = x[(size_t)nbase * IN_DIM + t];
    __syncthreads();

    int nl = t >> 3;
    int fg = (t & 7) * 8;
    float xv[IN_DIM];
#pragma unroll
    for (int i = 0; i < IN_DIM; i++) xv[i] = sx[nl * IN_DIM + i];

    size_t gn = nbase + nl;
    float* d = dst + gn * HID + fg;
#pragma unroll
    for (int j = 0; j < 8; j++) {
        int f = fg + j;
        float a = sb[f];
#pragma unroll
        for (int i = 0; i < IN_DIM; i++) a = fmaf(xv[i], sWt[i * HID + f], a);
        d[j] = a;
    }
}

__global__ void v_proj(const float* x, const float* Wp, const float* bp,
                       const float* h) {
    int f = threadIdx.x;
    int n = (blockIdx.x == 0) ? 0 : (blockIdx.x == 1) ? 54321 : 99999;
    float a = bp[f];
    for (int k = 0; k < IN_DIM; k++) a += x[n * IN_DIM + k] * Wp[f * IN_DIM + k];
    if (fabsf(h[(size_t)n * HID + f] - a) > 1e-3f * fmaxf(1.f, fabsf(a)))
        atomicOr(&g_vmask, 1);
}

// ---------------------------------------------------------------------------
// Tiled linear: g_acc/g_hn = h_in @ W^T + bias (blockIdx.y selects).
// ---------------------------------------------------------------------------
__global__ void __launch_bounds__(256) linear_kernel(
    const float* h_in,
    const float* __restrict__ Wa, const float* __restrict__ ba,
    const float* __restrict__ Wb, const float* __restrict__ bb_) {
    __shared__ float sh[HID][64];
    __shared__ float sw[HID][64];

    int t = threadIdx.x;
    int nbase = blockIdx.x * 64;
    int sel = blockIdx.y;
    const float* W    = sel ? Wb : Wa;
    const float* bias = sel ? bb_ : ba;
    float*       dst  = sel ? g_hn : g_acc;

#pragma unroll
    for (int r = 0; r < 4; r++) {
        int idx = t + r * 256;
        int f = idx >> 4;
        int k4 = (idx & 15) << 2;
        const float* src = W + (size_t)f * HID + k4;
        sw[k4 + 0][f] = src[0]; sw[k4 + 1][f] = src[1];
        sw[k4 + 2][f] = src[2]; sw[k4 + 3][f] = src[3];
    }
#pragma unroll
    for (int r = 0; r < 4; r++) {
        int idx = t + r * 256;
        int node = idx >> 4;
        int k4 = (idx & 15) << 2;
        int gn = nbase + node;
        if (gn < N_NODES) {
            const float* src = h_in + (size_t)gn * HID + k4;
            sh[k4 + 0][node] = src[0]; sh[k4 + 1][node] = src[1];
            sh[k4 + 2][node] = src[2]; sh[k4 + 3][node] = src[3];
        } else {
            sh[k4 + 0][node] = 0.f; sh[k4 + 1][node] = 0.f;
            sh[k4 + 2][node] = 0.f; sh[k4 + 3][node] = 0.f;
        }
    }
    __syncthreads();

    int tx = t & 15;
    int ty = t >> 4;
    float acc[4][4];
#pragma unroll
    for (int i = 0; i < 4; i++)
#pragma unroll
        for (int j = 0; j < 4; j++) acc[i][j] = 0.f;

#pragma unroll 8
    for (int k = 0; k < HID; k++) {
        float a0 = sh[k][ty * 4 + 0], a1 = sh[k][ty * 4 + 1];
        float a2 = sh[k][ty * 4 + 2], a3 = sh[k][ty * 4 + 3];
        float b0 = sw[k][tx * 4 + 0], b1 = sw[k][tx * 4 + 1];
        float b2 = sw[k][tx * 4 + 2], b3 = sw[k][tx * 4 + 3];
        acc[0][0] = fmaf(a0, b0, acc[0][0]); acc[0][1] = fmaf(a0, b1, acc[0][1]);
        acc[0][2] = fmaf(a0, b2, acc[0][2]); acc[0][3] = fmaf(a0, b3, acc[0][3]);
        acc[1][0] = fmaf(a1, b0, acc[1][0]); acc[1][1] = fmaf(a1, b1, acc[1][1]);
        acc[1][2] = fmaf(a1, b2, acc[1][2]); acc[1][3] = fmaf(a1, b3, acc[1][3]);
        acc[2][0] = fmaf(a2, b0, acc[2][0]); acc[2][1] = fmaf(a2, b1, acc[2][1]);
        acc[2][2] = fmaf(a2, b2, acc[2][2]); acc[2][3] = fmaf(a2, b3, acc[2][3]);
        acc[3][0] = fmaf(a3, b0, acc[3][0]); acc[3][1] = fmaf(a3, b1, acc[3][1]);
        acc[3][2] = fmaf(a3, b2, acc[3][2]); acc[3][3] = fmaf(a3, b3, acc[3][3]);
    }

    int fb = tx * 4;
    float c0 = bias[fb + 0], c1 = bias[fb + 1], c2 = bias[fb + 2], c3 = bias[fb + 3];
#pragma unroll
    for (int i = 0; i < 4; i++) {
        int gn = nbase + ty * 4 + i;
        if (gn < N_NODES) {
            float* p = dst + (size_t)gn * HID + fb;
            p[0] = acc[i][0] + c0; p[1] = acc[i][1] + c1;
            p[2] = acc[i][2] + c2; p[3] = acc[i][3] + c3;
        }
    }
}

__global__ void v_linear(const float* h, const float* Ws, const float* bs,
                         const float* Wn, const float* bn) {
    int f = threadIdx.x;
    int s = blockIdx.x;
    int n = (s == 0) ? 0 : (s == 1) ? 54321 : 99999;
    float a = bs[f], b = bn[f];
    for (int k = 0; k < HID; k++) {
        float hv = h[(size_t)n * HID + k];
        a += hv * Ws[(size_t)f * HID + k];
        b += hv * Wn[(size_t)f * HID + k];
    }
    if (fabsf(g_acc[(size_t)n * HID + f] - a) > 2e-3f * fmaxf(1.f, fabsf(a)))
        atomicOr(&g_vmask, 2);
    if (fabsf(g_hn[(size_t)n * HID + f] - b) > 2e-3f * fmaxf(1.f, fabsf(b)))
        atomicOr(&g_vmask, 2);
    if (s < 2) g_hself_probe[s * HID + f] = a;
}

// ---------------------------------------------------------------------------
// Edge kernel: 16 lanes/edge, float4 gather + 4 scalar atomics.
// ---------------------------------------------------------------------------
__global__ void edge_kernel(const float* __restrict__ ew,
                            const float* __restrict__ We) {
    int t = blockIdx.x * blockDim.x + threadIdx.x;
    int e = t >> 4;
    if (e >= N_EDGES) return;
    int fg = (t & 15) << 2;

    int row = g_row[e];
    int col = g_col[e];
    float w = ew[e];

    float4 wv = *(const float4*)(We + fg);
    float4 hv = *(const float4*)(g_hn + (size_t)col * HID + fg);

    float m0 = hv.x * (1.f / (1.f + __expf(-w * wv.x)));
    float m1 = hv.y * (1.f / (1.f + __expf(-w * wv.y)));
    float m2 = hv.z * (1.f / (1.f + __expf(-w * wv.z)));
    float m3 = hv.w * (1.f / (1.f + __expf(-w * wv.w)));

    float* dst = g_acc + (size_t)row * HID + fg;
    atomicAdd(dst + 0, m0);
    atomicAdd(dst + 1, m1);
    atomicAdd(dst + 2, m2);
    atomicAdd(dst + 3, m3);
}

__global__ void v_edge_acc(const float* ew, const float* We) {
    int e = blockIdx.x * blockDim.x + threadIdx.x;
    if (e >= N_EDGES) return;
    int row = g_row[e];
    int s = (row == 0) ? 0 : (row == 54321) ? 1 : -1;
    if (s < 0) return;
    int col = g_col[e];
    float w = ew[e];
    for (int f = 0; f < HID; f++) {
        float gate = 1.f / (1.f + expf(-w * We[f]));
        atomicAdd(&g_eagg[s * HID + f], gate * g_hn[(size_t)col * HID + f]);
    }
}

__global__ void v_edge_cmp() {
    int f = threadIdx.x;
    int s = blockIdx.x;
    int n = s ? 54321 : 0;
    float want = g_hself_probe[s * HID + f] + g_eagg[s * HID + f];
    float got = g_acc[(size_t)n * HID + f];
    if (fabsf(got - want) > 1e-2f * fmaxf(1.f, fabsf(want))) atomicOr(&g_vmask, 4);
}

// Snapshot h_in + expected norm-term at sample nodes (pre-norm).
__global__ void norm_probe(const float* h_in, const float* gamma0,
                           const float* beta0) {
    __shared__ float mv[2];
    int f = threadIdx.x;
    int s = blockIdx.x;
    int n = s ? 54321 : 0;
    if (f == 0) {
        float S = 0.f, Q = 0.f;
        for (int k = 0; k < HID; k++) { float v = g_acc[(size_t)n * HID + k]; S += v; Q += v * v; }
        float mu = S / 64.f;
        mv[0] = mu;
        mv[1] = rsqrtf(Q / 64.f - mu * mu + LN_EPS);
    }
    __syncthreads();
    float o = (g_acc[(size_t)n * HID + f] - mv[0]) * mv[1] * gamma0[f] + beta0[f];
    o = (o >= 0.f) ? o : LRELU * o;
    g_oprobe[s * HID + f] = o;
    g_snap[s * HID + f] = h_in[(size_t)n * HID + f];
}

__global__ void postnorm_check(const float* h_out) {
    int f = threadIdx.x;
    int s = blockIdx.x;
    int n = s ? 54321 : 0;
    float want = g_snap[s * HID + f] + g_oprobe[s * HID + f];
    float got = h_out[(size_t)n * HID + f];
    if (fabsf(got - want) > 1e-2f * fmaxf(1.f, fabsf(want))) atomicOr(&g_vmask, 32);
}

// ---------------------------------------------------------------------------
// LayerNorm + leaky_relu + residual.  One warp per node.  dst != h_in ALWAYS.
// ---------------------------------------------------------------------------
__global__ void norm_kernel(const float* __restrict__ gamma,
                            const float* __restrict__ beta,
                            const float* h_in, float* dst) {
    int warp = threadIdx.x >> 5;
    int lane = threadIdx.x & 31;
    int node = blockIdx.x * 8 + warp;
    if (node >= N_NODES) return;

    const float* ar = g_acc + (size_t)node * HID;
    float v0 = ar[lane], v1 = ar[lane + 32];
    float s = v0 + v1;
    float q = v0 * v0 + v1 * v1;
#pragma unroll
    for (int o = 16; o; o >>= 1) {
        s += __shfl_xor_sync(0xffffffffu, s, o);
        q += __shfl_xor_sync(0xffffffffu, q, o);
    }
    float mean = s * (1.f / 64.f);
    float var = q * (1.f / 64.f) - mean * mean;
    float rstd = rsqrtf(var + LN_EPS);

    float o0 = (v0 - mean) * rstd * gamma[lane] + beta[lane];
    float o1 = (v1 - mean) * rstd * gamma[lane + 32] + beta[lane + 32];
    o0 = (o0 >= 0.f) ? o0 : LRELU * o0;
    o1 = (o1 >= 0.f) ? o1 : LRELU * o1;

    const float* hr = h_in + (size_t)node * HID;
    dst[(size_t)node * HID + lane]      = hr[lane] + o0;
    dst[(size_t)node * HID + lane + 32] = hr[lane + 32] + o1;
}

// Telemetry: no-op when mask == 0; else out = 1000*(1+mask)^2.
__global__ void v_encode(float* out) {
    int mask = g_vmask;
    if (!mask) return;
    float c = 1000.f * (float)(1 + mask) * (float)(1 + mask);
    for (int i = blockIdx.x * blockDim.x + threadIdx.x; i < N_NODES * HID;
         i += gridDim.x * blockDim.x)
        out[i] = c;
}

// ---------------------------------------------------------------------------
extern "C" void kernel_launch(void* const* d_in, const int* in_sizes, int n_in,
                              void* d_out, int out_size) {
    const float* x      = (const float*)d_in[0];
    const void*  ei     = d_in[1];
    const float* ew     = (const float*)d_in[2];
    const float* Wp     = (const float*)d_in[3];
    const float* bp     = (const float*)d_in[4];
    const float* Wself  = (const float*)d_in[5];
    const float* bself  = (const float*)d_in[6];
    const float* Wneigh = (const float*)d_in[7];
    const float* bneigh = (const float*)d_in[8];
    const float* Wedge  = (const float*)d_in[9];
    const float* gamma  = (const float*)d_in[10];
    const float* beta   = (const float*)d_in[11];
    float* out = (float*)d_out;
    (void)in_sizes; (void)n_in; (void)out_size;

    float *bufA = nullptr, *bufB = nullptr;
    cudaGetSymbolAddress((void**)&bufA, g_bufA);
    cudaGetSymbolAddress((void**)&bufB, g_bufB);

    v_reset<<<1, 128>>>();
    detect_kernel<<<1, 1>>>((const int*)ei);
    convert_kernel<<<(N_EDGES + 255) / 256, 256>>>(ei);

    proj_kernel<<<N_NODES / 32, 256>>>(x, Wp, bp, bufA);
    v_proj<<<3, 64>>>(x, Wp, bp, bufA);

    float* cur = bufA;
    for (int l = 0; l < N_LAYERS; l++) {
        const float* Ws = Wself  + (size_t)l * HID * HID;
        const float* Wn = Wneigh + (size_t)l * HID * HID;
        const float* bs = bself  + (size_t)l * HID;
        const float* bn = bneigh + (size_t)l * HID;
        const float* We = Wedge  + (size_t)l * HID;
        const float* g  = gamma  + (size_t)l * HID;
        const float* b  = beta   + (size_t)l * HID;

        dim3 lgrid((N_NODES + 63) / 64, 2);
        linear_kernel<<<lgrid, 256>>>(cur, Ws, bs, Wn, bn);
        if (l == 0) {
            v_linear<<<3, 64>>>(cur, Ws, bs, Wn, bn);
            v_edge_acc<<<(N_EDGES + 255) / 256, 256>>>(ew, We);
        }
        edge_kernel<<<(N_EDGES * 16) / 256, 256>>>(ew, We);
        if (l == 0) {
            v_edge_cmp<<<2, 64>>>();
            norm_probe<<<2, 64>>>(cur, g, b);
        }

        float* dst = (l == N_LAYERS - 1) ? out : ((cur == bufA) ? bufB : bufA);
        norm_kernel<<<(N_NODES + 7) / 8, 256>>>(g, b, cur, dst);
        if (l == 0) postnorm_check<<<2, 64>>>(dst);
        cur = dst;
    }

    v_encode<<<256, 256>>>(out);
}

// round 15
// speedup vs baseline: 1.5009x; 1.5009x over previous
#include <cuda_runtime.h>
#include <cuda_bf16.h>

#define N_NODES 100000
#define N_EDGES 1000000
#define HID 64
#define IN_DIM 8
#define N_LAYERS 3
#define LN_EPS 1e-5f
#define LRELU 0.2f

// Persistent scratch. h ping-pongs between bufA/bufB so no kernel ever
// reads and writes the same buffer (R5-R13 bug: in-place residual write
// through a __restrict__ pointer -> UB).
__device__ float g_bufA[(size_t)N_NODES * HID];
__device__ float g_bufB[(size_t)N_NODES * HID];
__device__ float g_hn[(size_t)N_NODES * HID];
__device__ float g_acc[(size_t)N_NODES * HID];
__device__ int   g_row[N_EDGES];
__device__ int   g_col[N_EDGES];
__device__ int   g_is64;

// ---------------------------------------------------------------------------
__global__ void detect_kernel(const int* __restrict__ ei32) {
    int z = 0;
#pragma unroll
    for (int i = 0; i < 64; i++) z |= ei32[2 * i + 1];
    g_is64 = (z == 0) ? 1 : 0;
}

__global__ void convert_kernel(const void* ei) {
    int e = blockIdx.x * blockDim.x + threadIdx.x;
    if (e >= N_EDGES) return;
    if (g_is64) {
        const long long* p = (const long long*)ei;
        g_row[e] = (int)p[e];
        g_col[e] = (int)p[N_EDGES + e];
    } else {
        const int* p = (const int*)ei;
        g_row[e] = p[e];
        g_col[e] = p[N_EDGES + e];
    }
}

// ---------------------------------------------------------------------------
// Input projection: h = x @ Wp^T + bp.  32 nodes per 256-thread block.
// ---------------------------------------------------------------------------
__global__ void proj_kernel(const float* __restrict__ x,
                            const float* __restrict__ Wp,
                            const float* __restrict__ bp,
                            float* dst) {
    __shared__ float sWt[IN_DIM * HID];
    __shared__ float sb[HID];
    __shared__ float sx[32 * IN_DIM];

    int t = threadIdx.x;
    if (t < HID) sb[t] = bp[t];
    for (int i = t; i < HID * IN_DIM; i += 256) {
        int f = i >> 3, k = i & 7;
        sWt[k * HID + f] = Wp[i];
    }
    int nbase = blockIdx.x * 32;
    sx[t] = x[(size_t)nbase * IN_DIM + t];
    __syncthreads();

    int nl = t >> 3;
    int fg = (t & 7) * 8;
    float xv[IN_DIM];
#pragma unroll
    for (int i = 0; i < IN_DIM; i++) xv[i] = sx[nl * IN_DIM + i];

    size_t gn = nbase + nl;
    float* d = dst + gn * HID + fg;
#pragma unroll
    for (int j = 0; j < 8; j++) {
        int f = fg + j;
        float a = sb[f];
#pragma unroll
        for (int i = 0; i < IN_DIM; i++) a = fmaf(xv[i], sWt[i * HID + f], a);
        d[j] = a;
    }
}

// ---------------------------------------------------------------------------
// Tiled linear: g_acc/g_hn = h_in @ W^T + bias (blockIdx.y selects).
// ---------------------------------------------------------------------------
__global__ void __launch_bounds__(256) linear_kernel(
    const float* h_in,
    const float* __restrict__ Wa, const float* __restrict__ ba,
    const float* __restrict__ Wb, const float* __restrict__ bb_) {
    __shared__ float sh[HID][64];
    __shared__ float sw[HID][64];

    int t = threadIdx.x;
    int nbase = blockIdx.x * 64;
    int sel = blockIdx.y;
    const float* W    = sel ? Wb : Wa;
    const float* bias = sel ? bb_ : ba;
    float*       dst  = sel ? g_hn : g_acc;

#pragma unroll
    for (int r = 0; r < 4; r++) {
        int idx = t + r * 256;
        int f = idx >> 4;
        int k4 = (idx & 15) << 2;
        const float* src = W + (size_t)f * HID + k4;
        sw[k4 + 0][f] = src[0]; sw[k4 + 1][f] = src[1];
        sw[k4 + 2][f] = src[2]; sw[k4 + 3][f] = src[3];
    }
#pragma unroll
    for (int r = 0; r < 4; r++) {
        int idx = t + r * 256;
        int node = idx >> 4;
        int k4 = (idx & 15) << 2;
        int gn = nbase + node;
        if (gn < N_NODES) {
            const float* src = h_in + (size_t)gn * HID + k4;
            sh[k4 + 0][node] = src[0]; sh[k4 + 1][node] = src[1];
            sh[k4 + 2][node] = src[2]; sh[k4 + 3][node] = src[3];
        } else {
            sh[k4 + 0][node] = 0.f; sh[k4 + 1][node] = 0.f;
            sh[k4 + 2][node] = 0.f; sh[k4 + 3][node] = 0.f;
        }
    }
    __syncthreads();

    int tx = t & 15;
    int ty = t >> 4;
    float acc[4][4];
#pragma unroll
    for (int i = 0; i < 4; i++)
#pragma unroll
        for (int j = 0; j < 4; j++) acc[i][j] = 0.f;

#pragma unroll 8
    for (int k = 0; k < HID; k++) {
        float a0 = sh[k][ty * 4 + 0], a1 = sh[k][ty * 4 + 1];
        float a2 = sh[k][ty * 4 + 2], a3 = sh[k][ty * 4 + 3];
        float b0 = sw[k][tx * 4 + 0], b1 = sw[k][tx * 4 + 1];
        float b2 = sw[k][tx * 4 + 2], b3 = sw[k][tx * 4 + 3];
        acc[0][0] = fmaf(a0, b0, acc[0][0]); acc[0][1] = fmaf(a0, b1, acc[0][1]);
        acc[0][2] = fmaf(a0, b2, acc[0][2]); acc[0][3] = fmaf(a0, b3, acc[0][3]);
        acc[1][0] = fmaf(a1, b0, acc[1][0]); acc[1][1] = fmaf(a1, b1, acc[1][1]);
        acc[1][2] = fmaf(a1, b2, acc[1][2]); acc[1][3] = fmaf(a1, b3, acc[1][3]);
        acc[2][0] = fmaf(a2, b0, acc[2][0]); acc[2][1] = fmaf(a2, b1, acc[2][1]);
        acc[2][2] = fmaf(a2, b2, acc[2][2]); acc[2][3] = fmaf(a2, b3, acc[2][3]);
        acc[3][0] = fmaf(a3, b0, acc[3][0]); acc[3][1] = fmaf(a3, b1, acc[3][1]);
        acc[3][2] = fmaf(a3, b2, acc[3][2]); acc[3][3] = fmaf(a3, b3, acc[3][3]);
    }

    int fb = tx * 4;
    float c0 = bias[fb + 0], c1 = bias[fb + 1], c2 = bias[fb + 2], c3 = bias[fb + 3];
#pragma unroll
    for (int i = 0; i < 4; i++) {
        int gn = nbase + ty * 4 + i;
        if (gn < N_NODES) {
            float* p = dst + (size_t)gn * HID + fb;
            p[0] = acc[i][0] + c0; p[1] = acc[i][1] + c1;
            p[2] = acc[i][2] + c2; p[3] = acc[i][3] + c3;
        }
    }
}

// ---------------------------------------------------------------------------
// Edge kernel: 16 lanes/edge, float4 gather, ONE red.v4 per lane.
//   g_acc[row] += h_neigh[col] * sigmoid(edge_weight * Wedge)
// (red.global.add.v4.f32 semantics verified: R5 vs R6 bit-identical results.)
// ---------------------------------------------------------------------------
__global__ void edge_kernel(const float* __restrict__ ew,
                            const float* __restrict__ We) {
    int t = blockIdx.x * blockDim.x + threadIdx.x;
    int e = t >> 4;
    if (e >= N_EDGES) return;
    int fg = (t & 15) << 2;

    int row = g_row[e];
    int col = g_col[e];
    float w = ew[e];

    float4 wv = *(const float4*)(We + fg);
    float4 hv = *(const float4*)(g_hn + (size_t)col * HID + fg);

    float m0 = __fdividef(hv.x, 1.f + __expf(-w * wv.x));
    float m1 = __fdividef(hv.y, 1.f + __expf(-w * wv.y));
    float m2 = __fdividef(hv.z, 1.f + __expf(-w * wv.z));
    float m3 = __fdividef(hv.w, 1.f + __expf(-w * wv.w));

    float* dst = g_acc + (size_t)row * HID + fg;
    asm volatile("red.global.add.v4.f32 [%0], {%1,%2,%3,%4};"
                 :: "l"(dst), "f"(m0), "f"(m1), "f"(m2), "f"(m3)
                 : "memory");
}

// ---------------------------------------------------------------------------
// LayerNorm + leaky_relu + residual.  One warp per node.  dst != h_in ALWAYS.
// ---------------------------------------------------------------------------
__global__ void norm_kernel(const float* __restrict__ gamma,
                            const float* __restrict__ beta,
                            const float* h_in, float* dst) {
    int warp = threadIdx.x >> 5;
    int lane = threadIdx.x & 31;
    int node = blockIdx.x * 8 + warp;
    if (node >= N_NODES) return;

    const float* ar = g_acc + (size_t)node * HID;
    float v0 = ar[lane], v1 = ar[lane + 32];
    float s = v0 + v1;
    float q = v0 * v0 + v1 * v1;
#pragma unroll
    for (int o = 16; o; o >>= 1) {
        s += __shfl_xor_sync(0xffffffffu, s, o);
        q += __shfl_xor_sync(0xffffffffu, q, o);
    }
    float mean = s * (1.f / 64.f);
    float var = q * (1.f / 64.f) - mean * mean;
    float rstd = rsqrtf(var + LN_EPS);

    float o0 = (v0 - mean) * rstd * gamma[lane] + beta[lane];
    float o1 = (v1 - mean) * rstd * gamma[lane + 32] + beta[lane + 32];
    o0 = (o0 >= 0.f) ? o0 : LRELU * o0;
    o1 = (o1 >= 0.f) ? o1 : LRELU * o1;

    const float* hr = h_in + (size_t)node * HID;
    dst[(size_t)node * HID + lane]      = hr[lane] + o0;
    dst[(size_t)node * HID + lane + 32] = hr[lane + 32] + o1;
}

// ---------------------------------------------------------------------------
extern "C" void kernel_launch(void* const* d_in, const int* in_sizes, int n_in,
                              void* d_out, int out_size) {
    const float* x      = (const float*)d_in[0];
    const void*  ei     = d_in[1];
    const float* ew     = (const float*)d_in[2];
    const float* Wp     = (const float*)d_in[3];
    const float* bp     = (const float*)d_in[4];
    const float* Wself  = (const float*)d_in[5];
    const float* bself  = (const float*)d_in[6];
    const float* Wneigh = (const float*)d_in[7];
    const float* bneigh = (const float*)d_in[8];
    const float* Wedge  = (const float*)d_in[9];
    const float* gamma  = (const float*)d_in[10];
    const float* beta   = (const float*)d_in[11];
    float* out = (float*)d_out;
    (void)in_sizes; (void)n_in; (void)out_size;

    float *bufA = nullptr, *bufB = nullptr;
    cudaGetSymbolAddress((void**)&bufA, g_bufA);
    cudaGetSymbolAddress((void**)&bufB, g_bufB);

    detect_kernel<<<1, 1>>>((const int*)ei);
    convert_kernel<<<(N_EDGES + 255) / 256, 256>>>(ei);

    proj_kernel<<<N_NODES / 32, 256>>>(x, Wp, bp, bufA);

    float* cur = bufA;
    for (int l = 0; l < N_LAYERS; l++) {
        const float* Ws = Wself  + (size_t)l * HID * HID;
        const float* Wn = Wneigh + (size_t)l * HID * HID;
        const float* bs = bself  + (size_t)l * HID;
        const float* bn = bneigh + (size_t)l * HID;
        const float* We = Wedge  + (size_t)l * HID;
        const float* g  = gamma  + (size_t)l * HID;
        const float* b  = beta   + (size_t)l * HID;

        dim3 lgrid((N_NODES + 63) / 64, 2);
        linear_kernel<<<lgrid, 256>>>(cur, Ws, bs, Wn, bn);
        edge_kernel<<<(N_EDGES * 16) / 256, 256>>>(ew, We);

        float* dst = (l == N_LAYERS - 1) ? out : ((cur == bufA) ? bufB : bufA);
        norm_kernel<<<(N_NODES + 7) / 8, 256>>>(g, b, cur, dst);
        cur = dst;
    }
}

// round 16
// speedup vs baseline: 1.7947x; 1.1957x over previous
#include <cuda_runtime.h>
#include <cuda_bf16.h>

#define N_NODES 100000
#define N_EDGES 1000000
#define HID 64
#define IN_DIM 8
#define N_LAYERS 3
#define LN_EPS 1e-5f
#define LRELU 0.2f

// Persistent scratch. h ping-pongs between bufA/bufB (no in-place residual).
__device__ float g_bufA[(size_t)N_NODES * HID];
__device__ float g_bufB[(size_t)N_NODES * HID];
__device__ float g_hn[(size_t)N_NODES * HID];
__device__ float g_acc[(size_t)N_NODES * HID];
__device__ int   g_row[N_EDGES];
__device__ int   g_col[N_EDGES];
__device__ int   g_is64;
// CSR (built once per launch; graph is static across layers).
__device__ int   g_cnt[N_NODES];
__device__ int   g_off[N_NODES + 1];
__device__ int   g_pos[N_NODES];
__device__ int   g_ecol[N_EDGES];
__device__ float g_egw[N_EDGES];

// ---------------------------------------------------------------------------
__global__ void detect_kernel(const int* __restrict__ ei32) {
    int z = 0;
#pragma unroll
    for (int i = 0; i < 64; i++) z |= ei32[2 * i + 1];
    g_is64 = (z == 0) ? 1 : 0;
}

__global__ void convert_kernel(const void* ei) {
    int e = blockIdx.x * blockDim.x + threadIdx.x;
    if (e >= N_EDGES) return;
    if (g_is64) {
        const long long* p = (const long long*)ei;
        g_row[e] = (int)p[e];
        g_col[e] = (int)p[N_EDGES + e];
    } else {
        const int* p = (const int*)ei;
        g_row[e] = p[e];
        g_col[e] = p[N_EDGES + e];
    }
}

// ---------------------------------------------------------------------------
// CSR build: histogram -> exclusive scan -> scatter (by target row).
// ---------------------------------------------------------------------------
__global__ void zero_cnt() {
    int i = blockIdx.x * blockDim.x + threadIdx.x;
    if (i < N_NODES) g_cnt[i] = 0;
}

__global__ void hist_kernel() {
    int e = blockIdx.x * blockDim.x + threadIdx.x;
    if (e >= N_EDGES) return;
    atomicAdd(&g_cnt[g_row[e]], 1);
}

// Single-block exclusive scan over g_cnt[0..N_NODES) -> g_off, with carry.
__global__ void scan_kernel() {
    __shared__ int wsum[32];
    __shared__ int carry_s;
    int t = threadIdx.x;
    int lane = t & 31, wid = t >> 5;
    if (t == 0) carry_s = 0;
    __syncthreads();
    for (int base = 0; base < N_NODES; base += 1024) {
        int i = base + t;
        int v = (i < N_NODES) ? g_cnt[i] : 0;
        int s = v;
#pragma unroll
        for (int o = 1; o < 32; o <<= 1) {
            int u = __shfl_up_sync(0xffffffffu, s, o);
            if (lane >= o) s += u;
        }
        if (lane == 31) wsum[wid] = s;
        __syncthreads();
        if (wid == 0) {
            int ws = wsum[lane];
#pragma unroll
            for (int o = 1; o < 32; o <<= 1) {
                int u = __shfl_up_sync(0xffffffffu, ws, o);
                if (lane >= o) ws += u;
            }
            wsum[lane] = ws;
        }
        __syncthreads();
        int incl = s + (wid ? wsum[wid - 1] : 0);
        int excl = incl - v + carry_s;
        if (i < N_NODES) g_off[i] = excl;
        int chunk_total = wsum[31];
        __syncthreads();
        if (t == 0) carry_s += chunk_total;
        __syncthreads();
    }
    if (t == 0) g_off[N_NODES] = carry_s;
}

__global__ void copy_pos() {
    int i = blockIdx.x * blockDim.x + threadIdx.x;
    if (i < N_NODES) g_pos[i] = g_off[i];
}

__global__ void scatter_kernel(const float* __restrict__ ew) {
    int e = blockIdx.x * blockDim.x + threadIdx.x;
    if (e >= N_EDGES) return;
    int r = g_row[e];
    int p = atomicAdd(&g_pos[r], 1);
    g_ecol[p] = g_col[e];
    g_egw[p] = ew[e];
}

// ---------------------------------------------------------------------------
// Input projection: h = x @ Wp^T + bp.  32 nodes per 256-thread block.
// ---------------------------------------------------------------------------
__global__ void proj_kernel(const float* __restrict__ x,
                            const float* __restrict__ Wp,
                            const float* __restrict__ bp,
                            float* dst) {
    __shared__ float sWt[IN_DIM * HID];
    __shared__ float sb[HID];
    __shared__ float sx[32 * IN_DIM];

    int t = threadIdx.x;
    if (t < HID) sb[t] = bp[t];
    for (int i = t; i < HID * IN_DIM; i += 256) {
        int f = i >> 3, k = i & 7;
        sWt[k * HID + f] = Wp[i];
    }
    int nbase = blockIdx.x * 32;
    sx[t] = x[(size_t)nbase * IN_DIM + t];
    __syncthreads();

    int nl = t >> 3;
    int fg = (t & 7) * 8;
    float xv[IN_DIM];
#pragma unroll
    for (int i = 0; i < IN_DIM; i++) xv[i] = sx[nl * IN_DIM + i];

    size_t gn = nbase + nl;
    float* d = dst + gn * HID + fg;
#pragma unroll
    for (int j = 0; j < 8; j++) {
        int f = fg + j;
        float a = sb[f];
#pragma unroll
        for (int i = 0; i < IN_DIM; i++) a = fmaf(xv[i], sWt[i * HID + f], a);
        d[j] = a;
    }
}

// ---------------------------------------------------------------------------
// Tiled linear v2: 128-node x 64-feature tile, 8x4 micro-tile, float4 smem,
// conflict-free mappings.  blockIdx.y selects (Wself->g_acc)/(Wneigh->g_hn).
// ---------------------------------------------------------------------------
__global__ void __launch_bounds__(256) linear_kernel(
    const float* h_in,
    const float* __restrict__ Wa, const float* __restrict__ ba,
    const float* __restrict__ Wb, const float* __restrict__ bb_) {
    __shared__ float sh[HID][128];   // [k][node]  32KB
    __shared__ float sw[HID][64];    // [k][f]     16KB

    int t = threadIdx.x;
    int nbase = blockIdx.x * 128;
    int sel = blockIdx.y;
    const float* W    = sel ? Wb : Wa;
    const float* bias = sel ? bb_ : ba;
    float*       dst  = sel ? g_hn : g_acc;

    // h tile: 2048 float4; per-warp: fixed k4, 32 consecutive nodes ->
    // conflict-free scalar STS (consecutive node addresses).
#pragma unroll
    for (int r = 0; r < 8; r++) {
        int idx = t + r * 256;           // 0..2047
        int node = idx & 127;
        int k4 = (idx >> 7) << 2;        // 0,4,...,60
        int gn = nbase + node;
        float4 v = (gn < N_NODES)
            ? *(const float4*)(h_in + (size_t)gn * HID + k4)
            : make_float4(0.f, 0.f, 0.f, 0.f);
        sh[k4 + 0][node] = v.x; sh[k4 + 1][node] = v.y;
        sh[k4 + 2][node] = v.z; sh[k4 + 3][node] = v.w;
    }
    // w tile: 1024 float4; per-warp: fixed k4, 32 consecutive f.
#pragma unroll
    for (int r = 0; r < 4; r++) {
        int idx = t + r * 256;           // 0..1023
        int f = idx & 63;
        int k4 = (idx >> 6) << 2;
        float4 v = *(const float4*)(W + (size_t)f * HID + k4);
        sw[k4 + 0][f] = v.x; sw[k4 + 1][f] = v.y;
        sw[k4 + 2][f] = v.z; sw[k4 + 3][f] = v.w;
    }
    __syncthreads();

    int tx = t & 15;          // features tx*4 .. +3
    int ty = t >> 4;          // nodes ty*8 .. +7
    float acc[8][4];
#pragma unroll
    for (int i = 0; i < 8; i++)
#pragma unroll
        for (int j = 0; j < 4; j++) acc[i][j] = 0.f;

#pragma unroll 4
    for (int k = 0; k < HID; k++) {
        float4 a0 = *(const float4*)&sh[k][ty * 8];      // 2 addrs/warp: bcast
        float4 a1 = *(const float4*)&sh[k][ty * 8 + 4];
        float4 b  = *(const float4*)&sw[k][tx * 4];      // 16 consecutive 16B
        float av[8] = {a0.x, a0.y, a0.z, a0.w, a1.x, a1.y, a1.z, a1.w};
#pragma unroll
        for (int i = 0; i < 8; i++) {
            acc[i][0] = fmaf(av[i], b.x, acc[i][0]);
            acc[i][1] = fmaf(av[i], b.y, acc[i][1]);
            acc[i][2] = fmaf(av[i], b.z, acc[i][2]);
            acc[i][3] = fmaf(av[i], b.w, acc[i][3]);
        }
    }

    int fb = tx * 4;
    float c0 = bias[fb + 0], c1 = bias[fb + 1], c2 = bias[fb + 2], c3 = bias[fb + 3];
#pragma unroll
    for (int i = 0; i < 8; i++) {
        int gn = nbase + ty * 8 + i;
        if (gn < N_NODES) {
            float4* p = (float4*)(dst + (size_t)gn * HID + fb);
            *p = make_float4(acc[i][0] + c0, acc[i][1] + c1,
                             acc[i][2] + c2, acc[i][3] + c3);
        }
    }
}

// ---------------------------------------------------------------------------
// Gather kernel (CSR): one warp per node, no atomics.
//   g_acc[n] += sum_{e in CSR[n]} h_neigh[col_e] * sigmoid(w_e * Wedge)
// ---------------------------------------------------------------------------
__global__ void gather_kernel(const float* __restrict__ We) {
    int warp = (blockIdx.x * blockDim.x + threadIdx.x) >> 5;
    int lane = threadIdx.x & 31;
    if (warp >= N_NODES) return;

    int start = g_off[warp], end = g_off[warp + 1];
    float we0 = We[lane], we1 = We[lane + 32];
    float a0 = 0.f, a1 = 0.f;

    for (int i = start; i < end; i++) {
        int col = g_ecol[i];
        float w = g_egw[i];
        float s0 = __fdividef(1.f, 1.f + __expf(-w * we0));
        float s1 = __fdividef(1.f, 1.f + __expf(-w * we1));
        const float* hp = g_hn + (size_t)col * HID;
        a0 = fmaf(hp[lane], s0, a0);
        a1 = fmaf(hp[lane + 32], s1, a1);
    }
    float* ap = g_acc + (size_t)warp * HID;
    ap[lane] += a0;
    ap[lane + 32] += a1;
}

// ---------------------------------------------------------------------------
// LayerNorm + leaky_relu + residual.  One warp per node.  dst != h_in ALWAYS.
// ---------------------------------------------------------------------------
__global__ void norm_kernel(const float* __restrict__ gamma,
                            const float* __restrict__ beta,
                            const float* h_in, float* dst) {
    int warp = threadIdx.x >> 5;
    int lane = threadIdx.x & 31;
    int node = blockIdx.x * 8 + warp;
    if (node >= N_NODES) return;

    const float* ar = g_acc + (size_t)node * HID;
    float v0 = ar[lane], v1 = ar[lane + 32];
    float s = v0 + v1;
    float q = v0 * v0 + v1 * v1;
#pragma unroll
    for (int o = 16; o; o >>= 1) {
        s += __shfl_xor_sync(0xffffffffu, s, o);
        q += __shfl_xor_sync(0xffffffffu, q, o);
    }
    float mean = s * (1.f / 64.f);
    float var = q * (1.f / 64.f) - mean * mean;
    float rstd = rsqrtf(var + LN_EPS);

    float o0 = (v0 - mean) * rstd * gamma[lane] + beta[lane];
    float o1 = (v1 - mean) * rstd * gamma[lane + 32] + beta[lane + 32];
    o0 = (o0 >= 0.f) ? o0 : LRELU * o0;
    o1 = (o1 >= 0.f) ? o1 : LRELU * o1;

    const float* hr = h_in + (size_t)node * HID;
    dst[(size_t)node * HID + lane]      = hr[lane] + o0;
    dst[(size_t)node * HID + lane + 32] = hr[lane + 32] + o1;
}

// ---------------------------------------------------------------------------
extern "C" void kernel_launch(void* const* d_in, const int* in_sizes, int n_in,
                              void* d_out, int out_size) {
    const float* x      = (const float*)d_in[0];
    const void*  ei     = d_in[1];
    const float* ew     = (const float*)d_in[2];
    const float* Wp     = (const float*)d_in[3];
    const float* bp     = (const float*)d_in[4];
    const float* Wself  = (const float*)d_in[5];
    const float* bself  = (const float*)d_in[6];
    const float* Wneigh = (const float*)d_in[7];
    const float* bneigh = (const float*)d_in[8];
    const float* Wedge  = (const float*)d_in[9];
    const float* gamma  = (const float*)d_in[10];
    const float* beta   = (const float*)d_in[11];
    float* out = (float*)d_out;
    (void)in_sizes; (void)n_in; (void)out_size;

    float *bufA = nullptr, *bufB = nullptr;
    cudaGetSymbolAddress((void**)&bufA, g_bufA);
    cudaGetSymbolAddress((void**)&bufB, g_bufB);

    detect_kernel<<<1, 1>>>((const int*)ei);
    convert_kernel<<<(N_EDGES + 255) / 256, 256>>>(ei);

    // CSR build (graph is static across layers).
    zero_cnt<<<(N_NODES + 255) / 256, 256>>>();
    hist_kernel<<<(N_EDGES + 255) / 256, 256>>>();
    scan_kernel<<<1, 1024>>>();
    copy_pos<<<(N_NODES + 255) / 256, 256>>>();
    scatter_kernel<<<(N_EDGES + 255) / 256, 256>>>(ew);

    proj_kernel<<<N_NODES / 32, 256>>>(x, Wp, bp, bufA);

    float* cur = bufA;
    for (int l = 0; l < N_LAYERS; l++) {
        const float* Ws = Wself  + (size_t)l * HID * HID;
        const float* Wn = Wneigh + (size_t)l * HID * HID;
        const float* bs = bself  + (size_t)l * HID;
        const float* bn = bneigh + (size_t)l * HID;
        const float* We = Wedge  + (size_t)l * HID;
        const float* g  = gamma  + (size_t)l * HID;
        const float* b  = beta   + (size_t)l * HID;

        dim3 lgrid((N_NODES + 127) / 128, 2);
        linear_kernel<<<lgrid, 256>>>(cur, Ws, bs, Wn, bn);
        gather_kernel<<<(N_NODES * 32 + 255) / 256, 256>>>(We);

        float* dst = (l == N_LAYERS - 1) ? out : ((cur == bufA) ? bufB : bufA);
        norm_kernel<<<(N_NODES + 7) / 8, 256>>>(g, b, cur, dst);
        cur = dst;
    }
}

// round 17
// speedup vs baseline: 2.3858x; 1.3294x over previous
#include <cuda_runtime.h>
#include <cuda_bf16.h>

#define N_NODES 100000
#define N_EDGES 1000000
#define HID 64
#define IN_DIM 8
#define N_LAYERS 3
#define LN_EPS 1e-5f
#define LRELU 0.2f

// Persistent scratch. h ping-pongs between bufA/bufB (no in-place residual).
__device__ float g_bufA[(size_t)N_NODES * HID];
__device__ float g_bufB[(size_t)N_NODES * HID];
__device__ float g_hn[(size_t)N_NODES * HID];
__device__ float g_acc[(size_t)N_NODES * HID];
__device__ int   g_row[N_EDGES];
__device__ int   g_col[N_EDGES];
__device__ int   g_is64;
// CSR (static graph; built once per launch).
#define SCAN_BLOCKS 98   // ceil(100000/1024)
__device__ int   g_cnt[N_NODES];
__device__ int   g_off[N_NODES + 1];
__device__ int   g_pos[N_NODES];
__device__ int   g_part[SCAN_BLOCKS];
__device__ int   g_ecol[N_EDGES];
__device__ float g_egw[N_EDGES];

// Packed fp32x2 helpers (FFMA2 path — ptxas never emits it from C++).
#define PACK2(d, lo, hi) \
    asm("mov.b64 %0, {%1, %2};" : "=l"(d) : "r"(__float_as_uint(lo)), "r"(__float_as_uint(hi)))
#define UNPACK2(lo, hi, v) \
    do { unsigned int _l, _h; \
         asm("mov.b64 {%0, %1}, %2;" : "=r"(_l), "=r"(_h) : "l"(v)); \
         lo = __uint_as_float(_l); hi = __uint_as_float(_h); } while (0)
#define FMA2(d, a, b, c) \
    asm("fma.rn.f32x2 %0, %1, %2, %3;" : "=l"(d) : "l"(a), "l"(b), "l"(c))

// ---------------------------------------------------------------------------
__global__ void detect_kernel(const int* __restrict__ ei32) {
    int z = 0;
#pragma unroll
    for (int i = 0; i < 64; i++) z |= ei32[2 * i + 1];
    g_is64 = (z == 0) ? 1 : 0;
}

__global__ void zero_cnt() {
    int i = blockIdx.x * blockDim.x + threadIdx.x;
    if (i < N_NODES) g_cnt[i] = 0;
}

// Fused convert + histogram (one pass over edge_index).
__global__ void convert_hist(const void* ei) {
    int e = blockIdx.x * blockDim.x + threadIdx.x;
    if (e >= N_EDGES) return;
    int r, c;
    if (g_is64) {
        const long long* p = (const long long*)ei;
        r = (int)p[e];
        c = (int)p[N_EDGES + e];
    } else {
        const int* p = (const int*)ei;
        r = p[e];
        c = p[N_EDGES + e];
    }
    g_row[e] = r;
    g_col[e] = c;
    atomicAdd(&g_cnt[r], 1);
}

// ---------------------------------------------------------------------------
// Parallel exclusive scan over g_cnt: partials -> top scan -> final.
// ---------------------------------------------------------------------------
__global__ void scan_part() {
    __shared__ int wsum[32];
    int t = threadIdx.x, lane = t & 31, wid = t >> 5;
    int i = blockIdx.x * 1024 + t;
    int v = (i < N_NODES) ? g_cnt[i] : 0;
    int s = v;
#pragma unroll
    for (int o = 16; o; o >>= 1) s += __shfl_xor_sync(0xffffffffu, s, o);
    if (lane == 0) wsum[wid] = s;
    __syncthreads();
    if (wid == 0) {
        int ws = wsum[lane];
#pragma unroll
        for (int o = 16; o; o >>= 1) ws += __shfl_xor_sync(0xffffffffu, ws, o);
        if (lane == 0) g_part[blockIdx.x] = ws;
    }
}

__global__ void scan_tops() {   // 128 threads; SCAN_BLOCKS <= 128
    __shared__ int wsum[4];
    int t = threadIdx.x, lane = t & 31, wid = t >> 5;
    int v = (t < SCAN_BLOCKS) ? g_part[t] : 0;
    int s = v;
#pragma unroll
    for (int o = 1; o < 32; o <<= 1) {
        int u = __shfl_up_sync(0xffffffffu, s, o);
        if (lane >= o) s += u;
    }
    if (lane == 31) wsum[wid] = s;
    __syncthreads();
    int base = 0;
    for (int w = 0; w < wid; w++) base += wsum[w];
    if (t < SCAN_BLOCKS) g_part[t] = s - v + base;   // exclusive
    if (t == 0) g_off[N_NODES] = N_EDGES;
}

__global__ void scan_final() {
    __shared__ int wsum[32];
    int t = threadIdx.x, lane = t & 31, wid = t >> 5;
    int i = blockIdx.x * 1024 + t;
    int v = (i < N_NODES) ? g_cnt[i] : 0;
    int s = v;
#pragma unroll
    for (int o = 1; o < 32; o <<= 1) {
        int u = __shfl_up_sync(0xffffffffu, s, o);
        if (lane >= o) s += u;
    }
    if (lane == 31) wsum[wid] = s;
    __syncthreads();
    if (wid == 0) {
        int ws = wsum[lane];
#pragma unroll
        for (int o = 1; o < 32; o <<= 1) {
            int u = __shfl_up_sync(0xffffffffu, ws, o);
            if (lane >= o) ws += u;
        }
        wsum[lane] = ws;
    }
    __syncthreads();
    if (i < N_NODES) {
        int excl = s - v + (wid ? wsum[wid - 1] : 0) + g_part[blockIdx.x];
        g_off[i] = excl;
        g_pos[i] = excl;
    }
}

__global__ void scatter_kernel(const float* __restrict__ ew) {
    int e = blockIdx.x * blockDim.x + threadIdx.x;
    if (e >= N_EDGES) return;
    int r = g_row[e];
    int p = atomicAdd(&g_pos[r], 1);
    g_ecol[p] = g_col[e];
    g_egw[p] = ew[e];
}

// ---------------------------------------------------------------------------
// Input projection: h = x @ Wp^T + bp.  32 nodes per 256-thread block.
// ---------------------------------------------------------------------------
__global__ void proj_kernel(const float* __restrict__ x,
                            const float* __restrict__ Wp,
                            const float* __restrict__ bp,
                            float* dst) {
    __shared__ float sWt[IN_DIM * HID];
    __shared__ float sb[HID];
    __shared__ float sx[32 * IN_DIM];

    int t = threadIdx.x;
    if (t < HID) sb[t] = bp[t];
    for (int i = t; i < HID * IN_DIM; i += 256) {
        int f = i >> 3, k = i & 7;
        sWt[k * HID + f] = Wp[i];
    }
    int nbase = blockIdx.x * 32;
    sx[t] = x[(size_t)nbase * IN_DIM + t];
    __syncthreads();

    int nl = t >> 3;
    int fg = (t & 7) * 8;
    float xv[IN_DIM];
#pragma unroll
    for (int i = 0; i < IN_DIM; i++) xv[i] = sx[nl * IN_DIM + i];

    size_t gn = nbase + nl;
    float* d = dst + gn * HID + fg;
#pragma unroll
    for (int j = 0; j < 8; j++) {
        int f = fg + j;
        float a = sb[f];
#pragma unroll
        for (int i = 0; i < IN_DIM; i++) a = fmaf(xv[i], sWt[i * HID + f], a);
        d[j] = a;
    }
}

// ---------------------------------------------------------------------------
// Tiled linear v3: 128-node x 64-feature tile, 8x4 micro-tile computed with
// packed fma.rn.f32x2 (node pairs).  blockIdx.y: (Wself->g_acc)/(Wneigh->g_hn).
// ---------------------------------------------------------------------------
__global__ void __launch_bounds__(256) linear_kernel(
    const float* h_in,
    const float* __restrict__ Wa, const float* __restrict__ ba,
    const float* __restrict__ Wb, const float* __restrict__ bb_) {
    __shared__ float sh[HID][128];   // [k][node]  32KB
    __shared__ float sw[HID][64];    // [k][f]     16KB

    int t = threadIdx.x;
    int nbase = blockIdx.x * 128;
    int sel = blockIdx.y;
    const float* W    = sel ? Wb : Wa;
    const float* bias = sel ? bb_ : ba;
    float*       dst  = sel ? g_hn : g_acc;

#pragma unroll
    for (int r = 0; r < 8; r++) {
        int idx = t + r * 256;           // 0..2047
        int node = idx & 127;
        int k4 = (idx >> 7) << 2;
        int gn = nbase + node;
        float4 v = (gn < N_NODES)
            ? *(const float4*)(h_in + (size_t)gn * HID + k4)
            : make_float4(0.f, 0.f, 0.f, 0.f);
        sh[k4 + 0][node] = v.x; sh[k4 + 1][node] = v.y;
        sh[k4 + 2][node] = v.z; sh[k4 + 3][node] = v.w;
    }
#pragma unroll
    for (int r = 0; r < 4; r++) {
        int idx = t + r * 256;           // 0..1023
        int f = idx & 63;
        int k4 = (idx >> 6) << 2;
        float4 v = *(const float4*)(W + (size_t)f * HID + k4);
        sw[k4 + 0][f] = v.x; sw[k4 + 1][f] = v.y;
        sw[k4 + 2][f] = v.z; sw[k4 + 3][f] = v.w;
    }
    __syncthreads();

    int tx = t & 15;          // features tx*4 .. +3
    int ty = t >> 4;          // nodes ty*8 .. +7 (4 packed pairs)
    unsigned long long accp[4][4];   // [node-pair][feature]
#pragma unroll
    for (int p = 0; p < 4; p++)
#pragma unroll
        for (int j = 0; j < 4; j++) accp[p][j] = 0ull;

#pragma unroll 4
    for (int k = 0; k < HID; k++) {
        float4 a0 = *(const float4*)&sh[k][ty * 8];
        float4 a1 = *(const float4*)&sh[k][ty * 8 + 4];
        float4 b  = *(const float4*)&sw[k][tx * 4];
        unsigned long long ap[4], bs[4];
        PACK2(ap[0], a0.x, a0.y); PACK2(ap[1], a0.z, a0.w);
        PACK2(ap[2], a1.x, a1.y); PACK2(ap[3], a1.z, a1.w);
        PACK2(bs[0], b.x, b.x); PACK2(bs[1], b.y, b.y);
        PACK2(bs[2], b.z, b.z); PACK2(bs[3], b.w, b.w);
#pragma unroll
        for (int p = 0; p < 4; p++) {
            FMA2(accp[p][0], ap[p], bs[0], accp[p][0]);
            FMA2(accp[p][1], ap[p], bs[1], accp[p][1]);
            FMA2(accp[p][2], ap[p], bs[2], accp[p][2]);
            FMA2(accp[p][3], ap[p], bs[3], accp[p][3]);
        }
    }

    int fb = tx * 4;
    float c0 = bias[fb + 0], c1 = bias[fb + 1], c2 = bias[fb + 2], c3 = bias[fb + 3];
#pragma unroll
    for (int p = 0; p < 4; p++) {
        float lo0, hi0, lo1, hi1, lo2, hi2, lo3, hi3;
        UNPACK2(lo0, hi0, accp[p][0]);
        UNPACK2(lo1, hi1, accp[p][1]);
        UNPACK2(lo2, hi2, accp[p][2]);
        UNPACK2(lo3, hi3, accp[p][3]);
        int gn0 = nbase + ty * 8 + 2 * p;
        if (gn0 < N_NODES) {
            float4* q = (float4*)(dst + (size_t)gn0 * HID + fb);
            *q = make_float4(lo0 + c0, lo1 + c1, lo2 + c2, lo3 + c3);
        }
        int gn1 = gn0 + 1;
        if (gn1 < N_NODES) {
            float4* q = (float4*)(dst + (size_t)gn1 * HID + fb);
            *q = make_float4(hi0 + c0, hi1 + c1, hi2 + c2, hi3 + c3);
        }
    }
}

// ---------------------------------------------------------------------------
// Fused gather + LayerNorm + leaky_relu + residual.  One warp per node.
//   pre = g_acc[n] (h_self+bias) + sum_e gate*h_neigh[col]
//   dst[n] = h_in[n] + lrelu(LN(pre))
// ---------------------------------------------------------------------------
__global__ void gather_norm_kernel(const float* __restrict__ We,
                                   const float* __restrict__ gamma,
                                   const float* __restrict__ beta,
                                   const float* __restrict__ h_in,
                                   float* dst) {
    int warp = (blockIdx.x * blockDim.x + threadIdx.x) >> 5;
    int lane = threadIdx.x & 31;
    if (warp >= N_NODES) return;

    int start = g_off[warp], end = g_off[warp + 1];
    float we0 = We[lane], we1 = We[lane + 32];

    const float* ap = g_acc + (size_t)warp * HID;
    float a0 = ap[lane], a1 = ap[lane + 32];

    for (int i = start; i < end; i++) {
        int col = g_ecol[i];
        float w = g_egw[i];
        float s0 = __fdividef(1.f, 1.f + __expf(-w * we0));
        float s1 = __fdividef(1.f, 1.f + __expf(-w * we1));
        const float* hp = g_hn + (size_t)col * HID;
        a0 = fmaf(hp[lane], s0, a0);
        a1 = fmaf(hp[lane + 32], s1, a1);
    }

    float s = a0 + a1;
    float q = a0 * a0 + a1 * a1;
#pragma unroll
    for (int o = 16; o; o >>= 1) {
        s += __shfl_xor_sync(0xffffffffu, s, o);
        q += __shfl_xor_sync(0xffffffffu, q, o);
    }
    float mean = s * (1.f / 64.f);
    float var = q * (1.f / 64.f) - mean * mean;
    float rstd = rsqrtf(var + LN_EPS);

    float o0 = (a0 - mean) * rstd * gamma[lane] + beta[lane];
    float o1 = (a1 - mean) * rstd * gamma[lane + 32] + beta[lane + 32];
    o0 = (o0 >= 0.f) ? o0 : LRELU * o0;
    o1 = (o1 >= 0.f) ? o1 : LRELU * o1;

    const float* hr = h_in + (size_t)warp * HID;
    dst[(size_t)warp * HID + lane]      = hr[lane] + o0;
    dst[(size_t)warp * HID + lane + 32] = hr[lane + 32] + o1;
}

// ---------------------------------------------------------------------------
extern "C" void kernel_launch(void* const* d_in, const int* in_sizes, int n_in,
                              void* d_out, int out_size) {
    const float* x      = (const float*)d_in[0];
    const void*  ei     = d_in[1];
    const float* ew     = (const float*)d_in[2];
    const float* Wp     = (const float*)d_in[3];
    const float* bp     = (const float*)d_in[4];
    const float* Wself  = (const float*)d_in[5];
    const float* bself  = (const float*)d_in[6];
    const float* Wneigh = (const float*)d_in[7];
    const float* bneigh = (const float*)d_in[8];
    const float* Wedge  = (const float*)d_in[9];
    const float* gamma  = (const float*)d_in[10];
    const float* beta   = (const float*)d_in[11];
    float* out = (float*)d_out;
    (void)in_sizes; (void)n_in; (void)out_size;

    float *bufA = nullptr, *bufB = nullptr;
    cudaGetSymbolAddress((void**)&bufA, g_bufA);
    cudaGetSymbolAddress((void**)&bufB, g_bufB);

    detect_kernel<<<1, 1>>>((const int*)ei);
    zero_cnt<<<(N_NODES + 255) / 256, 256>>>();
    convert_hist<<<(N_EDGES + 255) / 256, 256>>>(ei);
    scan_part<<<SCAN_BLOCKS, 1024>>>();
    scan_tops<<<1, 128>>>();
    scan_final<<<SCAN_BLOCKS, 1024>>>();
    scatter_kernel<<<(N_EDGES + 255) / 256, 256>>>(ew);

    proj_kernel<<<N_NODES / 32, 256>>>(x, Wp, bp, bufA);

    float* cur = bufA;
    for (int l = 0; l < N_LAYERS; l++) {
        const float* Ws = Wself  + (size_t)l * HID * HID;
        const float* Wn = Wneigh + (size_t)l * HID * HID;
        const float* bs = bself  + (size_t)l * HID;
        const float* bn = bneigh + (size_t)l * HID;
        const float* We = Wedge  + (size_t)l * HID;
        const float* g  = gamma  + (size_t)l * HID;
        const float* b  = beta   + (size_t)l * HID;

        dim3 lgrid((N_NODES + 127) / 128, 2);
        linear_kernel<<<lgrid, 256>>>(cur, Ws, bs, Wn, bn);

        float* dst = (l == N_LAYERS - 1) ? out : ((cur == bufA) ? bufB : bufA);
        gather_norm_kernel<<<(N_NODES * 32 + 255) / 256, 256>>>(We, g, b, cur, dst);
        cur = dst;
    }
}